// round 10
// baseline (speedup 1.0000x reference)
#include <cuda_runtime.h>
#include <math.h>

#define NBOX 4096
#define WORDS 128   // NBOX/32
#define MM 20
#define HH 16
#define NLAB 4      // labels actually in {0,1,2}; 4th warp idles
#define POOLSM 8192 // smem pool window (entries)

// ---------------- device scratch ----------------
__device__ int            g_perm[NBOX];
__device__ float          g_boxes7[NBOX * 7];
__device__ float4         g_bev4[NBOX];
__device__ int            g_lab[NBOX];
__device__ unsigned int   g_sup0[WORDS];
__device__ unsigned int   g_labmask[NLAB * WORDS];
__device__ unsigned int   g_rows[NBOX * WORDS];        // only deg>31 rows valid
__device__ unsigned short g_pool[NBOX * 31];           // compacted neighbor lists
__device__ unsigned int   g_ofsdeg[NBOX];              // ofs(24) | min(deg,255)(8)
__device__ unsigned int   g_selfw[NBOX];               // own-word neighbor mask (diag cleared)
__device__ unsigned int   g_poolcnt;
__device__ int            g_tasks[NLAB * NBOX * 24];   // per-label regions
__device__ int            g_ntv[NLAB];
__device__ unsigned int   g_keep[WORDS];

__device__ __forceinline__ unsigned sort_key(float sc) {
    float f = (sc > 0.2f) ? sc : __int_as_float(0xff800000);
    unsigned b = __float_as_uint(f);
    unsigned u = (b & 0x80000000u) ? ~b : (b | 0x80000000u);
    return ~u;   // ascending == score descending
}

// ---------------- kernel 1: O(N^2) rank sort ----------------
__global__ void k_rank(const float* __restrict__ scores) {
    __shared__ unsigned sk[NBOX];
    int t = threadIdx.x;
    if (blockIdx.x == 0 && t == 0) g_poolcnt = 0;   // reset pool each launch
    for (int k = t; k < NBOX; k += blockDim.x) sk[k] = sort_key(scores[k]);
    __syncthreads();
    int i = blockIdx.x * blockDim.x + t;
    unsigned ki = sk[i];
    int rank = 0;
    const uint4* sk4 = (const uint4*)sk;
#pragma unroll 4
    for (int j4 = 0; j4 < NBOX / 4; j4++) {
        uint4 v = sk4[j4];
        int j = j4 * 4;
        rank += (v.x < ki) || (v.x == ki && j + 0 < i);
        rank += (v.y < ki) || (v.y == ki && j + 1 < i);
        rank += (v.z < ki) || (v.z == ki && j + 2 < i);
        rank += (v.w < ki) || (v.w == ki && j + 3 < i);
    }
    g_perm[rank] = i;
}

// ---------------- kernel 2: gather, BEV, label masks, prefill outputs ----------------
__global__ void k_prep(const float* __restrict__ pb, const float* __restrict__ ps,
                       const int* __restrict__ pl, float* __restrict__ out) {
    int s = blockIdx.x * blockDim.x + threadIdx.x;
    int o = g_perm[s];
    float b0 = pb[o*9+0], b1 = pb[o*9+1], b2 = pb[o*9+2];
    float b3 = pb[o*9+3], b4 = pb[o*9+4], b5 = pb[o*9+5];
    float b6 = pb[o*9+6], b7 = pb[o*9+7], b8 = pb[o*9+8];
    g_boxes7[s*7+0] = b0; g_boxes7[s*7+1] = b1; g_boxes7[s*7+2] = b2;
    g_boxes7[s*7+3] = b3; g_boxes7[s*7+4] = b4; g_boxes7[s*7+5] = b5;
    g_boxes7[s*7+6] = b6;
    out[s*9+0] = b0; out[s*9+1] = b1; out[s*9+2] = b2;
    out[s*9+3] = b3; out[s*9+4] = b4; out[s*9+5] = b5;
    out[s*9+6] = b6; out[s*9+7] = b7; out[s*9+8] = b8;

    const float PI = 3.14159265358979323846f;
    float ang = b6 - floorf(b6 / PI + 0.5f) * PI;
    bool sw = fabsf(ang) >= 0.25f * PI;
    float dx = sw ? b4 : b3;
    float dy = sw ? b3 : b4;
    g_bev4[s] = make_float4(b0 - dx * 0.5f, b1 - dy * 0.5f, b0 + dx * 0.5f, b1 + dy * 0.5f);

    int lab = pl[o];
    g_lab[s] = lab;
    float sc = ps[o];
    out[NBOX*9  + s] = sc;
    out[NBOX*10 + s] = (float)lab;

    unsigned inval = __ballot_sync(0xffffffffu, !(sc > 0.2f));
    if ((threadIdx.x & 31) == 0) g_sup0[s >> 5] = inval;
#pragma unroll
    for (int L = 0; L < NLAB; L++) {
        unsigned lm = __ballot_sync(0xffffffffu, lab == L);
        if ((threadIdx.x & 31) == 0) g_labmask[L * WORDS + (s >> 5)] = lm;
    }
}

// ---------------- kernel 3: adjacency + pool compaction + selfw ----------------
__global__ void __launch_bounds__(1024) k_adj() {
    __shared__ float4 sb[1024];
    __shared__ float  sa[1024];
    __shared__ float4 rb[32];
    __shared__ int    rl[32];
    int t = threadIdx.x;
    int R = blockIdx.x * 32;
    if (t < 32) { rb[t] = g_bev4[R + t]; rl[t] = g_lab[R + t]; }
    __syncthreads();
    int rloc = t >> 5;
    int r = R + rloc;
    int wl = t & 31;
    float4 a = rb[rloc];
    int la = rl[rloc];
    float aa = (a.z - a.x) * (a.w - a.y);
    int w0 = blockIdx.x;
    int T0 = w0 >> 5;

    unsigned mw[4] = {0, 0, 0, 0};
#pragma unroll
    for (int T = 0; T < 4; T++) {
        if (T >= T0) {
            float4 bb0 = g_bev4[T * 1024 + t];
            sb[t] = bb0;
            sa[t] = (bb0.z - bb0.x) * (bb0.w - bb0.y);
            __syncthreads();
            int w = T * 32 + wl;
            unsigned m = 0;
            if (w >= w0) {
                unsigned cand = g_labmask[la * WORDS + w];
                if (w == w0) cand &= 0xffffffffu << (r & 31);
                while (cand) {
                    int b = __ffs(cand) - 1; cand &= cand - 1;
                    int jj = wl * 32 + b;
                    float4 bb = sb[jj];
                    float xmin = fmaxf(a.x, bb.x), ymin = fmaxf(a.y, bb.y);
                    float xmax = fminf(a.z, bb.z), ymax = fminf(a.w, bb.w);
                    float inter = fmaxf(xmax - xmin, 0.f) * fmaxf(ymax - ymin, 0.f);
                    float iou = inter / fmaxf(aa + sa[jj] - inter, 1e-6f);
                    if (iou > 0.3f) m |= 1u << b;
                }
            }
            mw[T] = m;
            __syncthreads();
        }
    }

    // own-word neighbor mask (diag cleared) for the scan's rem update
    {
        unsigned own = (T0 == 0) ? mw[0] : (T0 == 1) ? mw[1] : (T0 == 2) ? mw[2] : mw[3];
        own = __shfl_sync(0xffffffffu, own, w0 & 31);
        if (wl == 0) g_selfw[r] = own & ~(1u << (r & 31));
    }

    int excl[4], tbase[4];
    int running = 0;
#pragma unroll
    for (int T = 0; T < 4; T++) {
        int pc = __popc(mw[T]);
        int incl = pc;
        for (int d = 1; d < 32; d <<= 1) {
            int n = __shfl_up_sync(0xffffffffu, incl, d);
            if (wl >= d) incl += n;
        }
        excl[T] = incl - pc;
        tbase[T] = running;
        running += __shfl_sync(0xffffffffu, incl, 31);
    }
    int deg = running - 1;            // diag always set
    int cap = deg < 31 ? deg : 31;

    unsigned base = 0;
    if (wl == 0 && deg > 0) base = atomicAdd(&g_poolcnt, (unsigned)cap);
    base = __shfl_sync(0xffffffffu, base, 0);

#pragma unroll
    for (int T = 0; T < 4; T++) {
        unsigned v = mw[T];
        int rank0 = tbase[T] + excl[T];   // global bit rank; diag is rank 0
        int wword = T * 32 + wl;
        while (v) {
            int b = __ffs(v) - 1; v &= v - 1;
            if (rank0 > 0 && rank0 - 1 < 31)
                g_pool[base + rank0 - 1] = (unsigned short)(wword * 32 + b);
            rank0++;
        }
    }
    if (wl == 0)
        g_ofsdeg[r] = base | ((unsigned)(deg > 255 ? 255 : deg) << 24);

    if (deg > 31) {
        g_rows[r * WORDS +       wl] = mw[0];
        g_rows[r * WORDS +  32 + wl] = mw[1];
        g_rows[r * WORDS +  64 + wl] = mw[2];
        g_rows[r * WORDS +  96 + wl] = mw[3];
    }
}

// ---------------- kernel 4: per-label scans — R7 structure, ALU cur via selfw ----------------
__global__ void __launch_bounds__(128) k_scanA() {
    __shared__ unsigned sup[WORDS];
    __shared__ unsigned kp[WORDS];
    __shared__ unsigned sdeg0[WORDS];
    __shared__ unsigned slabm[NLAB * WORDS];
    __shared__ unsigned sod[NBOX];              // 16 KB packed ofs|deg
    __shared__ unsigned short spool[POOLSM];    // 16 KB pool window
    int t = threadIdx.x;
    int L = t >> 5;
    int lane = t & 31;
    for (int k = t; k < WORDS; k += 128) { sup[k] = g_sup0[k]; kp[k] = 0u; }
    for (int k = t; k < NLAB * WORDS; k += 128) slabm[k] = g_labmask[k];
    for (int k = t; k < NBOX; k += 128) sod[k] = g_ofsdeg[k];
    for (int k = t; k < POOLSM / 2; k += 128)
        ((unsigned*)spool)[k] = ((const unsigned*)g_pool)[k];
    __syncthreads();
    {
        unsigned m = 0;
#pragma unroll 8
        for (int b = 0; b < 32; b++)
            m |= ((sod[t * 32 + b] >> 24) == 0u) ? (1u << b) : 0u;
        sdeg0[t] = m;
    }
    __syncthreads();
    const unsigned* labm = slabm + L * WORDS;

    int nt = 0;
    for (int w = 0; w < WORDS; w++) {
        unsigned lm = labm[w];
        if (!lm) continue;
        unsigned rem = ~sup[w] & lm;
        if (!rem) continue;
        unsigned d0v = sdeg0[w];
        unsigned kpw = 0;
        while (rem) {
            unsigned nond0 = rem & ~d0v;
            if (!nond0) { kpw |= rem; break; }
            int b = __ffs(nond0) - 1;
            kpw |= rem & ~(0xfffffffeu << b);
            int i = w * 32 + b;
            unsigned od = sod[i];
            unsigned cur = __ldg(&g_selfw[i]) & rem;   // ALU rem-advance, no warp collective
            int deg = od >> 24;
            int ofs = od & 0xffffff;
            if (deg <= 31) {
                bool val = lane < deg;
                int jn = 0;
                if (val) {
                    int p = ofs + lane;
                    jn = (p < POOLSM) ? (int)spool[p] : (int)g_pool[p];
                    val = ((sup[jn >> 5] >> (jn & 31)) & 1u) == 0u;
                }
                unsigned m = __ballot_sync(0xffffffffu, val);
                int cnt = __popc(m) + 1;
                if (val) atomicOr(&sup[jn >> 5], 1u << (jn & 31));
                if (cnt > 1) {
                    int base = (L * NBOX + nt) * 24;
                    if (lane == 0) { g_tasks[base] = i; g_tasks[base + 1] = cnt; g_tasks[base + 2] = i; }
                    if (val) {
                        int rank = __popc(m & ((1u << lane) - 1u));
                        if (rank < 19) g_tasks[base + 3 + rank] = jn;
                    }
                    nt++;
                }
            } else {
                // exact bitmap fallback (rare; g_rows dumped for deg>31)
                uint4 rv = ((const uint4*)(g_rows + (size_t)i * WORDS))[lane];
                int ww0 = i >> 5;
                unsigned r0 = (4*lane+0 >= ww0) ? rv.x : 0u;
                unsigned r1 = (4*lane+1 >= ww0) ? rv.y : 0u;
                unsigned r2 = (4*lane+2 >= ww0) ? rv.z : 0u;
                unsigned r3 = (4*lane+3 >= ww0) ? rv.w : 0u;
                unsigned n0 = r0 & ~sup[4*lane+0], n1 = r1 & ~sup[4*lane+1];
                unsigned n2 = r2 & ~sup[4*lane+2], n3 = r3 & ~sup[4*lane+3];
                if (n0) atomicOr(&sup[4*lane+0], n0);
                if (n1) atomicOr(&sup[4*lane+1], n1);
                if (n2) atomicOr(&sup[4*lane+2], n2);
                if (n3) atomicOr(&sup[4*lane+3], n3);
                int pc = __popc(n0) + __popc(n1) + __popc(n2) + __popc(n3);
                int incl = pc;
                for (int d = 1; d < 32; d <<= 1) {
                    int v = __shfl_up_sync(0xffffffffu, incl, d);
                    if (lane >= d) incl += v;
                }
                int cnt = __shfl_sync(0xffffffffu, incl, 31);   // includes diag i
                if (cnt > 1) {
                    int base = (L * NBOX + nt) * 24;
                    if (lane == 0) { g_tasks[base] = i; g_tasks[base + 1] = cnt; }
                    int start = incl - pc;
                    unsigned nn[4] = { n0, n1, n2, n3 };
#pragma unroll
                    for (int q = 0; q < 4; q++) {
                        unsigned v = nn[q];
                        while (v && start < 20) {
                            int bb = __ffs(v) - 1; v &= v - 1;
                            g_tasks[base + 2 + start] = (4 * lane + q) * 32 + bb;
                            start++;
                        }
                    }
                    nt++;
                }
            }
            rem &= ~cur & (0xfffffffeu << b);
            __syncwarp();
        }
        if (lane == 0 && kpw) atomicOr(&kp[w], kpw);
    }
    if (lane == 0) g_ntv[L] = nt;
    __syncthreads();
    for (int k = t; k < WORDS; k += 128) g_keep[k] = kp[k];
}

// ---------------- kernel 5: parallel merge MLP + keep flags ----------------
__global__ void __launch_bounds__(128) k_merge(
    const float* __restrict__ w1, const float* __restrict__ b1,
    const float* __restrict__ w2, const float* __restrict__ b2,
    const float* __restrict__ w3, const float* __restrict__ b3,
    float* __restrict__ out) {
    __shared__ float ob[140];
    __shared__ float h1[112], h2[112];
    __shared__ float sw1[320], sw2[256], sw3[16], sb1v[16], sb2v[16];
    __shared__ float sb3v;
    int t = threadIdx.x;

    if (blockIdx.x < 32) {
        int s = blockIdx.x * 128 + t;
        out[NBOX * 11 + s] = ((g_keep[s >> 5] >> (s & 31)) & 1u) ? 1.0f : 0.0f;
    }

    for (int k = t; k < 320; k += 128) sw1[k] = w1[k];
    for (int k = t; k < 256; k += 128) sw2[k] = w2[k];
    if (t < 16) { sw3[t] = w3[t]; sb1v[t] = b1[t]; sb2v[t] = b2[t]; }
    if (t == 0) sb3v = b3[0];
    __syncthreads();

    for (int L = 0; L < NLAB; L++) {
        int nt = g_ntv[L];
        for (int task = blockIdx.x; task < nt; task += gridDim.x) {
            int base = (L * NBOX + task) * 24;
            int i = g_tasks[base];
            int cnt = g_tasks[base + 1];
            int mc = cnt < 20 ? cnt : 20;
            for (int e = t; e < 140; e += 128) {
                int m = e / 7, d = e - m * 7;
                ob[e] = (m < mc) ? g_boxes7[g_tasks[base + 2 + m] * 7 + d] : 0.f;
            }
            __syncthreads();
            if (t < 112) {
                int r = t >> 4, c = t & 15;
                float s = sb1v[c];
#pragma unroll
                for (int k = 0; k < MM; k++) s += ob[k * 7 + r] * sw1[k * HH + c];
                h1[t] = fmaxf(s, 0.f);
            }
            __syncthreads();
            if (t < 112) {
                int r = t >> 4, c = t & 15;
                float s = sb2v[c];
#pragma unroll
                for (int k = 0; k < HH; k++) s += h1[(r << 4) + k] * sw2[k * HH + c];
                h2[t] = fmaxf(s, 0.f);
            }
            __syncthreads();
            if (t < 7) {
                float s = sb3v;
#pragma unroll
                for (int k = 0; k < HH; k++) s += h2[(t << 4) + k] * sw3[k];
                if (t >= 3 && t < 6) s = fmaxf(s, 1e-5f);
                out[i * 9 + t] = s;
            }
            __syncthreads();
        }
    }
}

// ---------------- launch ----------------
extern "C" void kernel_launch(void* const* d_in, const int* in_sizes, int n_in,
                              void* d_out, int out_size) {
    const float* pb = (const float*)d_in[0];
    const float* ps = (const float*)d_in[1];
    const int*   pl = (const int*)  d_in[2];
    const float* w1 = (const float*)d_in[3];
    const float* b1 = (const float*)d_in[4];
    const float* w2 = (const float*)d_in[5];
    const float* b2 = (const float*)d_in[6];
    const float* w3 = (const float*)d_in[7];
    const float* b3 = (const float*)d_in[8];
    float* out = (float*)d_out;

    k_rank  <<<32, 128>>>(ps);
    k_prep  <<<32, 128>>>(pb, ps, pl, out);
    k_adj   <<<128, 1024>>>();
    k_scanA <<<1, 128>>>();
    k_merge <<<256, 128>>>(w1, b1, w2, b2, w3, b3, out);
}

// round 11
// speedup vs baseline: 1.7470x; 1.7470x over previous
#include <cuda_runtime.h>
#include <math.h>

#define NBOX 4096
#define WORDS 128   // NBOX/32
#define MM 20
#define HH 16
#define NLAB 4

// ---------------- device scratch ----------------
__device__ int            g_perm[NBOX];
__device__ float          g_boxes7[NBOX * 7];
__device__ float4         g_bev4[NBOX];
__device__ int            g_lab[NBOX];
__device__ unsigned int   g_sup0[WORDS];              // invalid bits
__device__ unsigned int   g_labmask[NLAB * WORDS];
__device__ unsigned int   g_rows[NBOX * WORDS];       // only deg>31 rows valid
__device__ unsigned short g_pool[NBOX * 31];          // upper (j>i) neighbor lists, ascending
__device__ unsigned int   g_ofsdeg[NBOX];             // ofs(24) | min(deg,255)(8)
__device__ unsigned int   g_poolcnt;
__device__ unsigned short g_lolist[NBOX * 64];        // reverse (k<j) neighbor lists, unordered
__device__ int            g_deglo[NBOX];
__device__ int            g_suppr[NBOX];              // min kept smaller neighbor, -1 none
__device__ unsigned int   g_keep[WORDS];

__device__ __forceinline__ unsigned sort_key(float sc) {
    float f = (sc > 0.2f) ? sc : __int_as_float(0xff800000);
    unsigned b = __float_as_uint(f);
    unsigned u = (b & 0x80000000u) ? ~b : (b | 0x80000000u);
    return ~u;   // ascending == score descending
}

__device__ __forceinline__ float iou_of(float4 a, float aa, float4 bb) {
    float xmin = fmaxf(a.x, bb.x), ymin = fmaxf(a.y, bb.y);
    float xmax = fminf(a.z, bb.z), ymax = fminf(a.w, bb.w);
    float inter = fmaxf(xmax - xmin, 0.f) * fmaxf(ymax - ymin, 0.f);
    float ab = (bb.z - bb.x) * (bb.w - bb.y);
    return inter / fmaxf(aa + ab - inter, 1e-6f);
}

// ---------------- kernel 1: O(N^2) rank sort ----------------
__global__ void k_rank(const float* __restrict__ scores) {
    __shared__ unsigned sk[NBOX];
    int t = threadIdx.x;
    if (blockIdx.x == 0 && t == 0) g_poolcnt = 0;
    for (int k = t; k < NBOX; k += blockDim.x) sk[k] = sort_key(scores[k]);
    __syncthreads();
    int i = blockIdx.x * blockDim.x + t;
    unsigned ki = sk[i];
    int rank = 0;
    const uint4* sk4 = (const uint4*)sk;
#pragma unroll 4
    for (int j4 = 0; j4 < NBOX / 4; j4++) {
        uint4 v = sk4[j4];
        int j = j4 * 4;
        rank += (v.x < ki) || (v.x == ki && j + 0 < i);
        rank += (v.y < ki) || (v.y == ki && j + 1 < i);
        rank += (v.z < ki) || (v.z == ki && j + 2 < i);
        rank += (v.w < ki) || (v.w == ki && j + 3 < i);
    }
    g_perm[rank] = i;
}

// ---------------- kernel 2: gather, BEV, label masks, prefill ----------------
__global__ void k_prep(const float* __restrict__ pb, const float* __restrict__ ps,
                       const int* __restrict__ pl, float* __restrict__ out) {
    int s = blockIdx.x * blockDim.x + threadIdx.x;
    int o = g_perm[s];
    float b0 = pb[o*9+0], b1 = pb[o*9+1], b2 = pb[o*9+2];
    float b3 = pb[o*9+3], b4 = pb[o*9+4], b5 = pb[o*9+5];
    float b6 = pb[o*9+6], b7 = pb[o*9+7], b8 = pb[o*9+8];
    g_boxes7[s*7+0] = b0; g_boxes7[s*7+1] = b1; g_boxes7[s*7+2] = b2;
    g_boxes7[s*7+3] = b3; g_boxes7[s*7+4] = b4; g_boxes7[s*7+5] = b5;
    g_boxes7[s*7+6] = b6;
    out[s*9+0] = b0; out[s*9+1] = b1; out[s*9+2] = b2;
    out[s*9+3] = b3; out[s*9+4] = b4; out[s*9+5] = b5;
    out[s*9+6] = b6; out[s*9+7] = b7; out[s*9+8] = b8;

    const float PI = 3.14159265358979323846f;
    float ang = b6 - floorf(b6 / PI + 0.5f) * PI;
    bool sw = fabsf(ang) >= 0.25f * PI;
    float dx = sw ? b4 : b3;
    float dy = sw ? b3 : b4;
    g_bev4[s] = make_float4(b0 - dx * 0.5f, b1 - dy * 0.5f, b0 + dx * 0.5f, b1 + dy * 0.5f);

    int lab = pl[o];
    g_lab[s] = lab;
    g_deglo[s] = 0;                    // reset reverse-degree counters
    float sc = ps[o];
    out[NBOX*9  + s] = sc;
    out[NBOX*10 + s] = (float)lab;

    unsigned inval = __ballot_sync(0xffffffffu, !(sc > 0.2f));
    if ((threadIdx.x & 31) == 0) g_sup0[s >> 5] = inval;
#pragma unroll
    for (int L = 0; L < NLAB; L++) {
        unsigned lm = __ballot_sync(0xffffffffu, lab == L);
        if ((threadIdx.x & 31) == 0) g_labmask[L * WORDS + (s >> 5)] = lm;
    }
}

// ---------------- kernel 3: adjacency + upper lists + reverse appends ----------------
__global__ void __launch_bounds__(1024) k_adj() {
    __shared__ float4 sb[1024];
    __shared__ float  sa[1024];
    __shared__ float4 rb[32];
    __shared__ int    rl[32];
    int t = threadIdx.x;
    int R = blockIdx.x * 32;
    if (t < 32) { rb[t] = g_bev4[R + t]; rl[t] = g_lab[R + t]; }
    __syncthreads();
    int rloc = t >> 5;
    int r = R + rloc;
    int wl = t & 31;
    float4 a = rb[rloc];
    int la = rl[rloc];
    float aa = (a.z - a.x) * (a.w - a.y);
    int w0 = blockIdx.x;
    int T0 = w0 >> 5;

    unsigned mw[4] = {0, 0, 0, 0};
#pragma unroll
    for (int T = 0; T < 4; T++) {
        if (T >= T0) {
            float4 bb0 = g_bev4[T * 1024 + t];
            sb[t] = bb0;
            sa[t] = (bb0.z - bb0.x) * (bb0.w - bb0.y);
            __syncthreads();
            int w = T * 32 + wl;
            unsigned m = 0;
            if (w >= w0) {
                unsigned cand = g_labmask[la * WORDS + w];
                if (w == w0) cand &= 0xffffffffu << (r & 31);
                while (cand) {
                    int b = __ffs(cand) - 1; cand &= cand - 1;
                    int jj = wl * 32 + b;
                    float4 bb = sb[jj];
                    float xmin = fmaxf(a.x, bb.x), ymin = fmaxf(a.y, bb.y);
                    float xmax = fminf(a.z, bb.z), ymax = fminf(a.w, bb.w);
                    float inter = fmaxf(xmax - xmin, 0.f) * fmaxf(ymax - ymin, 0.f);
                    float iou = inter / fmaxf(aa + sa[jj] - inter, 1e-6f);
                    if (iou > 0.3f) m |= 1u << b;
                }
            }
            mw[T] = m;
            __syncthreads();
        }
    }

    int excl[4], tbase[4];
    int running = 0;
#pragma unroll
    for (int T = 0; T < 4; T++) {
        int pc = __popc(mw[T]);
        int incl = pc;
        for (int d = 1; d < 32; d <<= 1) {
            int n = __shfl_up_sync(0xffffffffu, incl, d);
            if (wl >= d) incl += n;
        }
        excl[T] = incl - pc;
        tbase[T] = running;
        running += __shfl_sync(0xffffffffu, incl, 31);
    }
    int deg = running - 1;            // diag always set
    int cap = deg < 31 ? deg : 31;

    unsigned base = 0;
    if (wl == 0 && deg > 0) base = atomicAdd(&g_poolcnt, (unsigned)cap);
    base = __shfl_sync(0xffffffffu, base, 0);

#pragma unroll
    for (int T = 0; T < 4; T++) {
        unsigned v = mw[T];
        int rank0 = tbase[T] + excl[T];   // diag is rank 0
        int wword = T * 32 + wl;
        while (v) {
            int b = __ffs(v) - 1; v &= v - 1;
            int j = wword * 32 + b;
            if (rank0 > 0) {
                if (rank0 - 1 < 31)
                    g_pool[base + rank0 - 1] = (unsigned short)j;
                int pos = atomicAdd(&g_deglo[j], 1);     // reverse edge j <- r
                if (pos < 64) g_lolist[j * 64 + pos] = (unsigned short)r;
            }
            rank0++;
        }
    }
    if (wl == 0)
        g_ofsdeg[r] = base | ((unsigned)(deg > 255 ? 255 : deg) << 24);

    if (deg > 31) {
        g_rows[r * WORDS +       wl] = mw[0];
        g_rows[r * WORDS +  32 + wl] = mw[1];
        g_rows[r * WORDS +  64 + wl] = mw[2];
        g_rows[r * WORDS +  96 + wl] = mw[3];
    }
}

// ---------------- kernel 4: kept-fixpoint + suppressor (1 block) ----------------
__global__ void __launch_bounds__(1024) k_fix() {
    __shared__ unsigned char status[NBOX];   // 0 unknown, 1 kept, 2 not-kept
    __shared__ int sdeglo[NBOX];
    __shared__ unsigned svalid[WORDS];
    __shared__ int s_changed;
    int t = threadIdx.x;
    if (t < WORDS) svalid[t] = ~g_sup0[t];
    for (int k = t; k < NBOX; k += 1024) sdeglo[k] = g_deglo[k];
    __syncthreads();
    for (int k = t; k < NBOX; k += 1024)
        status[k] = ((svalid[k >> 5] >> (k & 31)) & 1u) ? 0 : 2;
    __syncthreads();

    for (int it = 0; it < NBOX; it++) {
        if (t == 0) s_changed = 0;
        __syncthreads();
        int ch = 0;
        for (int j = t; j < NBOX; j += 1024) {
            if (status[j] != 0) continue;
            int n = sdeglo[j];
            int st = 0;
            if (n <= 64) {
                bool anyK = false, allR = true;
                const unsigned short* ll = g_lolist + j * 64;
                for (int k = 0; k < n; k++) {
                    unsigned char s = status[ll[k]];
                    anyK |= (s == 1); allR &= (s != 0);
                }
                st = anyK ? 2 : (allR ? 1 : 0);
            } else {
                // exact fallback: rescan all smaller same-label boxes
                float4 a = g_bev4[j]; int la = g_lab[j];
                float aa = (a.z - a.x) * (a.w - a.y);
                bool anyK = false, allR = true;
                for (int k = 0; k < j; k++) {
                    if (g_lab[k] != la) continue;
                    if (iou_of(a, aa, g_bev4[k]) > 0.3f) {
                        unsigned char s = status[k];
                        anyK |= (s == 1); allR &= (s != 0);
                    }
                }
                st = anyK ? 2 : (allR ? 1 : 0);
            }
            if (st) { status[j] = (unsigned char)st; ch = 1; }
        }
        if (ch) s_changed = 1;
        __syncthreads();
        int cont = s_changed;
        __syncthreads();
        if (!cont) break;
    }

    // suppressor = min kept smaller neighbor (for suppressed valid boxes)
    for (int j = t; j < NBOX; j += 1024) {
        int sup = -1;
        if (status[j] == 2 && ((svalid[j >> 5] >> (j & 31)) & 1u)) {
            int n = sdeglo[j];
            int mn = 0x7fffffff;
            if (n <= 64) {
                const unsigned short* ll = g_lolist + j * 64;
                for (int k = 0; k < n; k++) {
                    int u = ll[k];
                    if (status[u] == 1 && u < mn) mn = u;
                }
            } else {
                float4 a = g_bev4[j]; int la = g_lab[j];
                float aa = (a.z - a.x) * (a.w - a.y);
                for (int k = 0; k < j; k++) {
                    if (g_lab[k] != la || status[k] != 1) continue;
                    if (iou_of(a, aa, g_bev4[k]) > 0.3f) { mn = k; break; }
                }
            }
            sup = mn;
        }
        g_suppr[j] = sup;
    }
    if (t < WORDS) {
        unsigned kw = 0;
#pragma unroll 8
        for (int b = 0; b < 32; b++)
            kw |= (status[t * 32 + b] == 1) ? (1u << b) : 0u;
        g_keep[t] = kw;
    }
}

// ---------------- kernel 5: parallel merge MLP + keep flags ----------------
__global__ void __launch_bounds__(128) k_merge(
    const float* __restrict__ w1, const float* __restrict__ b1,
    const float* __restrict__ w2, const float* __restrict__ b2,
    const float* __restrict__ w3, const float* __restrict__ b3,
    float* __restrict__ out) {
    __shared__ float ob[140];
    __shared__ float h1[112], h2[112];
    __shared__ float sw1[320], sw2[256], sw3[16], sb1v[16], sb2v[16];
    __shared__ float sb3v;
    __shared__ int scand[20];
    __shared__ int s_cnt;
    int t = threadIdx.x;

    if (blockIdx.x < 32) {
        int s = blockIdx.x * 128 + t;
        out[NBOX * 11 + s] = ((g_keep[s >> 5] >> (s & 31)) & 1u) ? 1.0f : 0.0f;
    }

    for (int k = t; k < 320; k += 128) sw1[k] = w1[k];
    for (int k = t; k < 256; k += 128) sw2[k] = w2[k];
    if (t < 16) { sw3[t] = w3[t]; sb1v[t] = b1[t]; sb2v[t] = b2[t]; }
    if (t == 0) sb3v = b3[0];
    __syncthreads();

    for (int i = blockIdx.x; i < NBOX; i += gridDim.x) {
        if (!((g_keep[i >> 5] >> (i & 31)) & 1u)) continue;
        unsigned od = g_ofsdeg[i];
        int deg = od >> 24;
        if (deg == 0) continue;

        if (t < 32) {
            if (deg <= 31) {
                bool sel = false; int j = 0;
                if (t < deg) {
                    j = (int)g_pool[(od & 0xffffff) + t];
                    sel = (g_suppr[j] == i);
                }
                unsigned m = __ballot_sync(0xffffffffu, sel);
                if (t == 0) { s_cnt = __popc(m) + 1; scand[0] = i; }
                if (sel) {
                    int rk = __popc(m & ((1u << t) - 1u));
                    if (rk < 19) scand[1 + rk] = j;
                }
            } else {
                uint4 rv = ((const uint4*)(g_rows + (size_t)i * WORDS))[t];
                int ww0 = i >> 5;
                unsigned mm[4];
#pragma unroll
                for (int q = 0; q < 4; q++) {
                    int w = t * 4 + q;
                    unsigned v = (q == 0) ? rv.x : (q == 1) ? rv.y : (q == 2) ? rv.z : rv.w;
                    if (w < ww0) v = 0;
                    if (w == ww0) v &= (0xfffffffeu << (i & 31));   // strictly > i
                    unsigned sel = 0;
                    while (v) {
                        int b = __ffs(v) - 1; v &= v - 1;
                        if (g_suppr[w * 32 + b] == i) sel |= 1u << b;
                    }
                    mm[q] = sel;
                }
                int pc = __popc(mm[0]) + __popc(mm[1]) + __popc(mm[2]) + __popc(mm[3]);
                int incl = pc;
                for (int d = 1; d < 32; d <<= 1) {
                    int v = __shfl_up_sync(0xffffffffu, incl, d);
                    if (t >= d) incl += v;
                }
                int total = __shfl_sync(0xffffffffu, incl, 31);
                int start = incl - pc;
#pragma unroll
                for (int q = 0; q < 4; q++) {
                    unsigned v = mm[q];
                    while (v) {
                        int b = __ffs(v) - 1; v &= v - 1;
                        if (start < 19) scand[1 + start] = (t * 4 + q) * 32 + b;
                        start++;
                    }
                }
                if (t == 0) { s_cnt = total + 1; scand[0] = i; }
            }
        }
        __syncthreads();
        int cnt = s_cnt;
        if (cnt > 1) {
            int mc = cnt < 20 ? cnt : 20;
            for (int e = t; e < 140; e += 128) {
                int m = e / 7, d = e - m * 7;
                ob[e] = (m < mc) ? g_boxes7[scand[m] * 7 + d] : 0.f;
            }
            __syncthreads();
            if (t < 112) {
                int r = t >> 4, c = t & 15;
                float s = sb1v[c];
#pragma unroll
                for (int k = 0; k < MM; k++) s += ob[k * 7 + r] * sw1[k * HH + c];
                h1[t] = fmaxf(s, 0.f);
            }
            __syncthreads();
            if (t < 112) {
                int r = t >> 4, c = t & 15;
                float s = sb2v[c];
#pragma unroll
                for (int k = 0; k < HH; k++) s += h1[(r << 4) + k] * sw2[k * HH + c];
                h2[t] = fmaxf(s, 0.f);
            }
            __syncthreads();
            if (t < 7) {
                float s = sb3v;
#pragma unroll
                for (int k = 0; k < HH; k++) s += h2[(t << 4) + k] * sw3[k];
                if (t >= 3 && t < 6) s = fmaxf(s, 1e-5f);
                out[i * 9 + t] = s;
            }
        }
        __syncthreads();
    }
}

// ---------------- launch ----------------
extern "C" void kernel_launch(void* const* d_in, const int* in_sizes, int n_in,
                              void* d_out, int out_size) {
    const float* pb = (const float*)d_in[0];
    const float* ps = (const float*)d_in[1];
    const int*   pl = (const int*)  d_in[2];
    const float* w1 = (const float*)d_in[3];
    const float* b1 = (const float*)d_in[4];
    const float* w2 = (const float*)d_in[5];
    const float* b2 = (const float*)d_in[6];
    const float* w3 = (const float*)d_in[7];
    const float* b3 = (const float*)d_in[8];
    float* out = (float*)d_out;

    k_rank  <<<32, 128>>>(ps);
    k_prep  <<<32, 128>>>(pb, ps, pl, out);
    k_adj   <<<128, 1024>>>();
    k_fix   <<<1, 1024>>>();
    k_merge <<<256, 128>>>(w1, b1, w2, b2, w3, b3, out);
}

// round 12
// speedup vs baseline: 2.1060x; 1.2055x over previous
#include <cuda_runtime.h>
#include <math.h>

#define NBOX 4096
#define WORDS 128   // NBOX/32
#define MM 20
#define HH 16
#define NLAB 4

// ---------------- device scratch ----------------
__device__ int            g_rankpart[2 * NBOX];
__device__ float          g_boxes7[NBOX * 7];
__device__ float4         g_bev4[NBOX];
__device__ int            g_lab[NBOX];
__device__ unsigned int   g_sup0[WORDS];              // invalid bits
__device__ unsigned int   g_labmask[NLAB * WORDS];
__device__ unsigned int   g_rows[NBOX * WORDS];       // only deg>31 rows valid
__device__ unsigned short g_pool[NBOX * 31];          // upper (j>i) neighbor lists, ascending
__device__ unsigned int   g_ofsdeg[NBOX];             // ofs(24) | min(deg,255)(8)
__device__ unsigned int   g_poolcnt;
__device__ unsigned short g_lolist4[NBOX * 4];        // first 4 reverse neighbors
__device__ unsigned short g_lolist[NBOX * 64];        // reverse overflow (pos 4..63)
__device__ int            g_deglo[NBOX];
__device__ int            g_suppr[NBOX];              // min kept smaller neighbor, -1 none
__device__ unsigned int   g_keep[WORDS];
__device__ int            g_mtask[NBOX];
__device__ int            g_nmt;

__device__ __forceinline__ unsigned sort_key(float sc) {
    float f = (sc > 0.2f) ? sc : __int_as_float(0xff800000);
    unsigned b = __float_as_uint(f);
    unsigned u = (b & 0x80000000u) ? ~b : (b | 0x80000000u);
    return ~u;   // ascending == score descending
}

__device__ __forceinline__ float iou_of(float4 a, float aa, float4 bb) {
    float xmin = fmaxf(a.x, bb.x), ymin = fmaxf(a.y, bb.y);
    float xmax = fminf(a.z, bb.z), ymax = fminf(a.w, bb.w);
    float inter = fmaxf(xmax - xmin, 0.f) * fmaxf(ymax - ymin, 0.f);
    float ab = (bb.z - bb.x) * (bb.w - bb.y);
    return inter / fmaxf(aa + ab - inter, 1e-6f);
}

// ---------------- kernel 1: split-j rank sort + global zero-init ----------------
__global__ void k_rank(const float* __restrict__ scores) {
    __shared__ unsigned sk[NBOX / 2];
    int t = threadIdx.x;
    int gid = blockIdx.x * 128 + t;          // 0..8191
    if (gid < NBOX) g_deglo[gid] = 0;
    if (gid < WORDS) g_sup0[gid] = 0;
    if (gid < NLAB * WORDS) g_labmask[gid] = 0;
    if (gid == 0) { g_poolcnt = 0; g_nmt = 0; }

    int half = blockIdx.x >> 5;              // 0 or 1
    int jo = half * (NBOX / 2);
    for (int k = t; k < NBOX / 2; k += 128) sk[k] = sort_key(scores[jo + k]);
    __syncthreads();
    int i = (blockIdx.x & 31) * 128 + t;
    unsigned ki = sort_key(scores[i]);
    int rank = 0;
    const uint4* sk4 = (const uint4*)sk;
#pragma unroll 4
    for (int j4 = 0; j4 < NBOX / 8; j4++) {
        uint4 v = sk4[j4];
        int j = jo + j4 * 4;
        rank += (v.x < ki) || (v.x == ki && j + 0 < i);
        rank += (v.y < ki) || (v.y == ki && j + 1 < i);
        rank += (v.z < ki) || (v.z == ki && j + 2 < i);
        rank += (v.w < ki) || (v.w == ki && j + 3 < i);
    }
    g_rankpart[half * NBOX + i] = rank;
}

// ---------------- kernel 2: scatter gather, BEV, label masks, prefill ----------------
__global__ void k_prep(const float* __restrict__ pb, const float* __restrict__ ps,
                       const int* __restrict__ pl, float* __restrict__ out) {
    int o = blockIdx.x * blockDim.x + threadIdx.x;   // original index
    int s = g_rankpart[o] + g_rankpart[NBOX + o];    // sorted position
    float b0 = pb[o*9+0], b1 = pb[o*9+1], b2 = pb[o*9+2];
    float b3 = pb[o*9+3], b4 = pb[o*9+4], b5 = pb[o*9+5];
    float b6 = pb[o*9+6], b7 = pb[o*9+7], b8 = pb[o*9+8];
    g_boxes7[s*7+0] = b0; g_boxes7[s*7+1] = b1; g_boxes7[s*7+2] = b2;
    g_boxes7[s*7+3] = b3; g_boxes7[s*7+4] = b4; g_boxes7[s*7+5] = b5;
    g_boxes7[s*7+6] = b6;
    out[s*9+0] = b0; out[s*9+1] = b1; out[s*9+2] = b2;
    out[s*9+3] = b3; out[s*9+4] = b4; out[s*9+5] = b5;
    out[s*9+6] = b6; out[s*9+7] = b7; out[s*9+8] = b8;

    const float PI = 3.14159265358979323846f;
    float ang = b6 - floorf(b6 / PI + 0.5f) * PI;
    bool sw = fabsf(ang) >= 0.25f * PI;
    float dx = sw ? b4 : b3;
    float dy = sw ? b3 : b4;
    g_bev4[s] = make_float4(b0 - dx * 0.5f, b1 - dy * 0.5f, b0 + dx * 0.5f, b1 + dy * 0.5f);

    int lab = pl[o];
    g_lab[s] = lab;
    float sc = ps[o];
    out[NBOX*9  + s] = sc;
    out[NBOX*10 + s] = (float)lab;

    if (!(sc > 0.2f)) atomicOr(&g_sup0[s >> 5], 1u << (s & 31));
    atomicOr(&g_labmask[lab * WORDS + (s >> 5)], 1u << (s & 31));
}

// ---------------- kernel 3: adjacency + upper lists + reverse appends ----------------
__global__ void __launch_bounds__(1024) k_adj() {
    __shared__ float4 sb[1024];
    __shared__ float  sa[1024];
    __shared__ float4 rb[32];
    __shared__ int    rl[32];
    int t = threadIdx.x;
    int R = blockIdx.x * 32;
    if (t < 32) { rb[t] = g_bev4[R + t]; rl[t] = g_lab[R + t]; }
    __syncthreads();
    int rloc = t >> 5;
    int r = R + rloc;
    int wl = t & 31;
    float4 a = rb[rloc];
    int la = rl[rloc];
    float aa = (a.z - a.x) * (a.w - a.y);
    int w0 = blockIdx.x;
    int T0 = w0 >> 5;

    unsigned mw[4] = {0, 0, 0, 0};
#pragma unroll
    for (int T = 0; T < 4; T++) {
        if (T >= T0) {
            float4 bb0 = g_bev4[T * 1024 + t];
            sb[t] = bb0;
            sa[t] = (bb0.z - bb0.x) * (bb0.w - bb0.y);
            __syncthreads();
            int w = T * 32 + wl;
            unsigned m = 0;
            if (w >= w0) {
                unsigned cand = g_labmask[la * WORDS + w];
                if (w == w0) cand &= 0xffffffffu << (r & 31);
                while (cand) {
                    int b = __ffs(cand) - 1; cand &= cand - 1;
                    int jj = wl * 32 + b;
                    if (iou_of(a, aa, sb[jj]) > 0.3f) m |= 1u << b;
                }
            }
            mw[T] = m;
            __syncthreads();
        }
    }

    int excl[4], tbase[4];
    int running = 0;
#pragma unroll
    for (int T = 0; T < 4; T++) {
        int pc = __popc(mw[T]);
        int incl = pc;
        for (int d = 1; d < 32; d <<= 1) {
            int n = __shfl_up_sync(0xffffffffu, incl, d);
            if (wl >= d) incl += n;
        }
        excl[T] = incl - pc;
        tbase[T] = running;
        running += __shfl_sync(0xffffffffu, incl, 31);
    }
    int deg = running - 1;            // diag always set
    int cap = deg < 31 ? deg : 31;

    unsigned base = 0;
    if (wl == 0 && deg > 0) base = atomicAdd(&g_poolcnt, (unsigned)cap);
    base = __shfl_sync(0xffffffffu, base, 0);

#pragma unroll
    for (int T = 0; T < 4; T++) {
        unsigned v = mw[T];
        int rank0 = tbase[T] + excl[T];   // diag is rank 0
        int wword = T * 32 + wl;
        while (v) {
            int b = __ffs(v) - 1; v &= v - 1;
            int j = wword * 32 + b;
            if (rank0 > 0) {
                if (rank0 - 1 < 31)
                    g_pool[base + rank0 - 1] = (unsigned short)j;
                int pos = atomicAdd(&g_deglo[j], 1);     // reverse edge j <- r
                if (pos < 4) g_lolist4[j * 4 + pos] = (unsigned short)r;
                else if (pos < 64) g_lolist[j * 64 + pos] = (unsigned short)r;
            }
            rank0++;
        }
    }
    if (wl == 0)
        g_ofsdeg[r] = base | ((unsigned)(deg > 255 ? 255 : deg) << 24);

    if (deg > 31) {
        g_rows[r * WORDS +       wl] = mw[0];
        g_rows[r * WORDS +  32 + wl] = mw[1];
        g_rows[r * WORDS +  64 + wl] = mw[2];
        g_rows[r * WORDS +  96 + wl] = mw[3];
    }
}

// ---------------- kernel 4: kept-fixpoint + suppressor (1 block, smem-resident) ----------------
__global__ void __launch_bounds__(1024) k_fix() {
    __shared__ unsigned char status[NBOX];   // 0 unknown, 1 kept, 2 not-kept
    __shared__ unsigned char sdeglo[NBOX];
    __shared__ unsigned short slo4[NBOX * 4];   // 32 KB inline reverse lists
    __shared__ unsigned svalid[WORDS];
    __shared__ int s_changed;
    int t = threadIdx.x;
    if (t < WORDS) svalid[t] = ~g_sup0[t];
    for (int k = t; k < NBOX; k += 1024) {
        int n = g_deglo[k];
        sdeglo[k] = (unsigned char)(n > 255 ? 255 : n);
    }
    for (int k = t; k < NBOX / 2; k += 1024)           // 2048 uint4 = 32 KB
        ((uint4*)slo4)[k] = ((const uint4*)g_lolist4)[k];
    __syncthreads();
    for (int k = t; k < NBOX; k += 1024)
        status[k] = ((svalid[k >> 5] >> (k & 31)) & 1u) ? 0 : 2;
    __syncthreads();

    for (int it = 0; it < NBOX; it++) {
        if (t == 0) s_changed = 0;
        __syncthreads();
        int ch = 0;
        for (int j = t; j < NBOX; j += 1024) {
            if (status[j] != 0) continue;
            int n = sdeglo[j];
            int st = 0;
            if (n <= 64) {
                bool anyK = false, allR = true;
                for (int k = 0; k < n; k++) {
                    int u = (k < 4) ? slo4[j * 4 + k] : g_lolist[j * 64 + k];
                    unsigned char s = status[u];
                    anyK |= (s == 1); allR &= (s != 0);
                }
                st = anyK ? 2 : (allR ? 1 : 0);
            } else {
                float4 a = g_bev4[j]; int la = g_lab[j];
                float aa = (a.z - a.x) * (a.w - a.y);
                bool anyK = false, allR = true;
                for (int k = 0; k < j; k++) {
                    if (g_lab[k] != la) continue;
                    if (iou_of(a, aa, g_bev4[k]) > 0.3f) {
                        unsigned char s = status[k];
                        anyK |= (s == 1); allR &= (s != 0);
                    }
                }
                st = anyK ? 2 : (allR ? 1 : 0);
            }
            if (st) { status[j] = (unsigned char)st; ch = 1; }
        }
        if (ch) s_changed = 1;
        __syncthreads();
        int cont = s_changed;
        __syncthreads();
        if (!cont) break;
    }

    // suppressor = min kept smaller neighbor + merge-task compaction
    for (int j = t; j < NBOX; j += 1024) {
        int sup = -1;
        if (status[j] == 2 && ((svalid[j >> 5] >> (j & 31)) & 1u)) {
            int n = sdeglo[j];
            int mn = 0x7fffffff;
            if (n <= 64) {
                for (int k = 0; k < n; k++) {
                    int u = (k < 4) ? slo4[j * 4 + k] : g_lolist[j * 64 + k];
                    if (status[u] == 1 && u < mn) mn = u;
                }
            } else {
                float4 a = g_bev4[j]; int la = g_lab[j];
                float aa = (a.z - a.x) * (a.w - a.y);
                for (int k = 0; k < j; k++) {
                    if (g_lab[k] != la || status[k] != 1) continue;
                    if (iou_of(a, aa, g_bev4[k]) > 0.3f) { mn = k; break; }
                }
            }
            sup = mn;
        }
        g_suppr[j] = sup;
        if (status[j] == 1 && (g_ofsdeg[j] >> 24) > 0)
            g_mtask[atomicAdd(&g_nmt, 1)] = j;
    }
    if (t < WORDS) {
        unsigned kw = 0;
#pragma unroll 8
        for (int b = 0; b < 32; b++)
            kw |= (status[t * 32 + b] == 1) ? (1u << b) : 0u;
        g_keep[t] = kw;
    }
}

// ---------------- kernel 5: parallel merge MLP + keep flags ----------------
__global__ void __launch_bounds__(128) k_merge(
    const float* __restrict__ w1, const float* __restrict__ b1,
    const float* __restrict__ w2, const float* __restrict__ b2,
    const float* __restrict__ w3, const float* __restrict__ b3,
    float* __restrict__ out) {
    __shared__ float ob[140];
    __shared__ float h1[112], h2[112];
    __shared__ float sw1[320], sw2[256], sw3[16], sb1v[16], sb2v[16];
    __shared__ float sb3v;
    __shared__ int scand[20];
    __shared__ int s_cnt;
    int t = threadIdx.x;

    if (blockIdx.x < 32) {
        int s = blockIdx.x * 128 + t;
        out[NBOX * 11 + s] = ((g_keep[s >> 5] >> (s & 31)) & 1u) ? 1.0f : 0.0f;
    }

    for (int k = t; k < 320; k += 128) sw1[k] = w1[k];
    for (int k = t; k < 256; k += 128) sw2[k] = w2[k];
    if (t < 16) { sw3[t] = w3[t]; sb1v[t] = b1[t]; sb2v[t] = b2[t]; }
    if (t == 0) sb3v = b3[0];
    __syncthreads();

    int nm = g_nmt;
    for (int task = blockIdx.x; task < nm; task += gridDim.x) {
        int i = g_mtask[task];
        unsigned od = g_ofsdeg[i];
        int deg = od >> 24;

        if (t < 32) {
            if (deg <= 31) {
                bool sel = false; int j = 0;
                if (t < deg) {
                    j = (int)g_pool[(od & 0xffffff) + t];
                    sel = (g_suppr[j] == i);
                }
                unsigned m = __ballot_sync(0xffffffffu, sel);
                if (t == 0) { s_cnt = __popc(m) + 1; scand[0] = i; }
                if (sel) {
                    int rk = __popc(m & ((1u << t) - 1u));
                    if (rk < 19) scand[1 + rk] = j;
                }
            } else {
                uint4 rv = ((const uint4*)(g_rows + (size_t)i * WORDS))[t];
                int ww0 = i >> 5;
                unsigned mm[4];
#pragma unroll
                for (int q = 0; q < 4; q++) {
                    int w = t * 4 + q;
                    unsigned v = (q == 0) ? rv.x : (q == 1) ? rv.y : (q == 2) ? rv.z : rv.w;
                    if (w < ww0) v = 0;
                    if (w == ww0) v &= (0xfffffffeu << (i & 31));   // strictly > i
                    unsigned sel = 0;
                    while (v) {
                        int b = __ffs(v) - 1; v &= v - 1;
                        if (g_suppr[w * 32 + b] == i) sel |= 1u << b;
                    }
                    mm[q] = sel;
                }
                int pc = __popc(mm[0]) + __popc(mm[1]) + __popc(mm[2]) + __popc(mm[3]);
                int incl = pc;
                for (int d = 1; d < 32; d <<= 1) {
                    int v = __shfl_up_sync(0xffffffffu, incl, d);
                    if (t >= d) incl += v;
                }
                int total = __shfl_sync(0xffffffffu, incl, 31);
                int start = incl - pc;
#pragma unroll
                for (int q = 0; q < 4; q++) {
                    unsigned v = mm[q];
                    while (v) {
                        int b = __ffs(v) - 1; v &= v - 1;
                        if (start < 19) scand[1 + start] = (t * 4 + q) * 32 + b;
                        start++;
                    }
                }
                if (t == 0) { s_cnt = total + 1; scand[0] = i; }
            }
        }
        __syncthreads();
        int cnt = s_cnt;
        if (cnt > 1) {
            int mc = cnt < 20 ? cnt : 20;
            for (int e = t; e < 140; e += 128) {
                int m = e / 7, d = e - m * 7;
                ob[e] = (m < mc) ? g_boxes7[scand[m] * 7 + d] : 0.f;
            }
            __syncthreads();
            if (t < 112) {
                int r = t >> 4, c = t & 15;
                float s = sb1v[c];
#pragma unroll
                for (int k = 0; k < MM; k++) s += ob[k * 7 + r] * sw1[k * HH + c];
                h1[t] = fmaxf(s, 0.f);
            }
            __syncthreads();
            if (t < 112) {
                int r = t >> 4, c = t & 15;
                float s = sb2v[c];
#pragma unroll
                for (int k = 0; k < HH; k++) s += h1[(r << 4) + k] * sw2[k * HH + c];
                h2[t] = fmaxf(s, 0.f);
            }
            __syncthreads();
            if (t < 7) {
                float s = sb3v;
#pragma unroll
                for (int k = 0; k < HH; k++) s += h2[(t << 4) + k] * sw3[k];
                if (t >= 3 && t < 6) s = fmaxf(s, 1e-5f);
                out[i * 9 + t] = s;
            }
        }
        __syncthreads();
    }
}

// ---------------- launch ----------------
extern "C" void kernel_launch(void* const* d_in, const int* in_sizes, int n_in,
                              void* d_out, int out_size) {
    const float* pb = (const float*)d_in[0];
    const float* ps = (const float*)d_in[1];
    const int*   pl = (const int*)  d_in[2];
    const float* w1 = (const float*)d_in[3];
    const float* b1 = (const float*)d_in[4];
    const float* w2 = (const float*)d_in[5];
    const float* b2 = (const float*)d_in[6];
    const float* w3 = (const float*)d_in[7];
    const float* b3 = (const float*)d_in[8];
    float* out = (float*)d_out;

    k_rank  <<<64, 128>>>(ps);
    k_prep  <<<32, 128>>>(pb, ps, pl, out);
    k_adj   <<<128, 1024>>>();
    k_fix   <<<1, 1024>>>();
    k_merge <<<256, 128>>>(w1, b1, w2, b2, w3, b3, out);
}